// round 14
// baseline (speedup 1.0000x reference)
#include <cuda_runtime.h>
#include <cstdint>

#define IN_F   8192
#define OUT_F  8192
#define THR    50.0f
#define NT     256
#define VPT    (IN_F / (NT * 8))  // 4 × 256-bit vectors per thread per row
#define HV     (VPT / 2)          // elig vectors split across the barrier

struct F8 { float v[8]; };

__device__ __forceinline__ F8 ldcs8(const float* p) {
    F8 r;
    asm volatile("ld.global.cs.v8.f32 {%0,%1,%2,%3,%4,%5,%6,%7}, [%8];"
                 : "=f"(r.v[0]), "=f"(r.v[1]), "=f"(r.v[2]), "=f"(r.v[3]),
                   "=f"(r.v[4]), "=f"(r.v[5]), "=f"(r.v[6]), "=f"(r.v[7])
                 : "l"(p));
    return r;
}
__device__ __forceinline__ void stcs8(float* p, const F8& r) {
    asm volatile("st.global.cs.v8.f32 [%0], {%1,%2,%3,%4,%5,%6,%7,%8};"
                 :: "l"(p),
                    "f"(r.v[0]), "f"(r.v[1]), "f"(r.v[2]), "f"(r.v[3]),
                    "f"(r.v[4]), "f"(r.v[5]), "f"(r.v[6]), "f"(r.v[7])
                 : "memory");
}

__global__ __launch_bounds__(NT, 5)   // regs capped at 48 -> 5 CTAs/SM
void snn_v8_kernel(const float* __restrict__ x,
                   const float* __restrict__ syn,
                   const float* __restrict__ mp,
                   const float* __restrict__ thr,
                   const float* __restrict__ elig,
                   float* __restrict__ out) {
    __shared__ float red[NT / 32];
    const int o = blockIdx.x;
    const int t = threadIdx.x;

    const float4* x4 = reinterpret_cast<const float4*>(x);   // 32 KB, L1-resident
    const float*  sr = syn  + (size_t)o * IN_F;
    const float*  er = elig + (size_t)o * IN_F;

    // ── Phase 1: full-row burst of syn via 4 × 256-bit loads ──
    F8 s[VPT];
    #pragma unroll
    for (int j = 0; j < VPT; j++)
        s[j] = ldcs8(sr + (size_t)(t + j * NT) * 8);

    float a0 = 0.0f, a1 = 0.0f, a2 = 0.0f, a3 = 0.0f;
    #pragma unroll
    for (int j = 0; j < VPT; j++) {
        const int vi = (t + j * NT) * 2;            // float4 index of this 32B chunk
        float4 xa = __ldg(&x4[vi]);
        float4 xb = __ldg(&x4[vi + 1]);
        a0 += (s[j].v[0] > THR ? xa.x : 0.0f) + (s[j].v[4] > THR ? xb.x : 0.0f);
        a1 += (s[j].v[1] > THR ? xa.y : 0.0f) + (s[j].v[5] > THR ? xb.y : 0.0f);
        a2 += (s[j].v[2] > THR ? xa.z : 0.0f) + (s[j].v[6] > THR ? xb.z : 0.0f);
        a3 += (s[j].v[3] > THR ? xa.w : 0.0f) + (s[j].v[7] > THR ? xb.w : 0.0f);
    }

    // First half of elig burst — in flight across the reduce/barrier
    F8 e[HV];
    #pragma unroll
    for (int j = 0; j < HV; j++)
        e[j] = ldcs8(er + (size_t)(t + j * NT) * 8);

    float acc = (a0 + a1) + (a2 + a3);
    #pragma unroll
    for (int off = 16; off > 0; off >>= 1)
        acc += __shfl_down_sync(0xffffffffu, acc, off);
    if ((t & 31) == 0) red[t >> 5] = acc;
    __syncthreads();                                // elig half still in flight

    // Second half issued immediately post-barrier
    F8 e2[HV];
    #pragma unroll
    for (int j = 0; j < HV; j++)
        e2[j] = ldcs8(er + (size_t)(t + (HV + j) * NT) * 8);

    float cur = 0.0f;
    #pragma unroll
    for (int w = 0; w < NT / 32; w++) cur += red[w];
    const float v  = __ldg(mp + o) * 0.6f + cur;
    const float sp = (v >= __ldg(thr + o)) ? 1.0f : 0.0f;
    if (t == 0) {
        out[o] = sp;                                // spikes
        out[OUT_F + o] = v * (1.0f - sp) * 0.3f;    // v_new
    }

    // ── Phase 2: consume → trace via 256-bit stores ──
    float* tr = out + 2 * (size_t)OUT_F + (size_t)o * IN_F;
    #pragma unroll
    for (int j = 0; j < HV; j++) {
        const int vi = (t + j * NT) * 2;
        float4 xa = __ldg(&x4[vi]);
        float4 xb = __ldg(&x4[vi + 1]);
        F8 r;
        r.v[0] = fminf(fmaxf(fmaf(e[j].v[0], 0.7f, sp * xa.x), 0.0f), 3.0f);
        r.v[1] = fminf(fmaxf(fmaf(e[j].v[1], 0.7f, sp * xa.y), 0.0f), 3.0f);
        r.v[2] = fminf(fmaxf(fmaf(e[j].v[2], 0.7f, sp * xa.z), 0.0f), 3.0f);
        r.v[3] = fminf(fmaxf(fmaf(e[j].v[3], 0.7f, sp * xa.w), 0.0f), 3.0f);
        r.v[4] = fminf(fmaxf(fmaf(e[j].v[4], 0.7f, sp * xb.x), 0.0f), 3.0f);
        r.v[5] = fminf(fmaxf(fmaf(e[j].v[5], 0.7f, sp * xb.y), 0.0f), 3.0f);
        r.v[6] = fminf(fmaxf(fmaf(e[j].v[6], 0.7f, sp * xb.z), 0.0f), 3.0f);
        r.v[7] = fminf(fmaxf(fmaf(e[j].v[7], 0.7f, sp * xb.w), 0.0f), 3.0f);
        stcs8(tr + (size_t)(t + j * NT) * 8, r);
    }
    #pragma unroll
    for (int j = 0; j < HV; j++) {
        const int vi = (t + (HV + j) * NT) * 2;
        float4 xa = __ldg(&x4[vi]);
        float4 xb = __ldg(&x4[vi + 1]);
        F8 r;
        r.v[0] = fminf(fmaxf(fmaf(e2[j].v[0], 0.7f, sp * xa.x), 0.0f), 3.0f);
        r.v[1] = fminf(fmaxf(fmaf(e2[j].v[1], 0.7f, sp * xa.y), 0.0f), 3.0f);
        r.v[2] = fminf(fmaxf(fmaf(e2[j].v[2], 0.7f, sp * xa.z), 0.0f), 3.0f);
        r.v[3] = fminf(fmaxf(fmaf(e2[j].v[3], 0.7f, sp * xa.w), 0.0f), 3.0f);
        r.v[4] = fminf(fmaxf(fmaf(e2[j].v[4], 0.7f, sp * xb.x), 0.0f), 3.0f);
        r.v[5] = fminf(fmaxf(fmaf(e2[j].v[5], 0.7f, sp * xb.y), 0.0f), 3.0f);
        r.v[6] = fminf(fmaxf(fmaf(e2[j].v[6], 0.7f, sp * xb.z), 0.0f), 3.0f);
        r.v[7] = fminf(fmaxf(fmaf(e2[j].v[7], 0.7f, sp * xb.w), 0.0f), 3.0f);
        stcs8(tr + (size_t)(t + (HV + j) * NT) * 8, r);
    }
}

extern "C" void kernel_launch(void* const* d_in, const int* in_sizes, int n_in,
                              void* d_out, int out_size) {
    const float* x    = (const float*)d_in[0];  // spike_input [1, 8192]
    const float* syn  = (const float*)d_in[1];  // synapse_states [8192, 8192]
    const float* mp   = (const float*)d_in[2];  // membrane_potential [8192]
    const float* thr  = (const float*)d_in[3];  // adaptive_threshold [8192]
    const float* elig = (const float*)d_in[4];  // eligibility_trace [8192, 8192]
    float* out = (float*)d_out;                 // [spikes | v_new | trace_new]

    snn_v8_kernel<<<OUT_F, NT>>>(x, syn, mp, thr, elig, out);
}

// round 15
// speedup vs baseline: 1.0066x; 1.0066x over previous
#include <cuda_runtime.h>
#include <cstdint>

#define IN_F   8192
#define OUT_F  8192
#define THR    50.0f
#define NT     256
#define NV     (IN_F / 4)         // 2048 float4 per row
#define FPT    (NV / NT)          // 8 float4 per thread — one burst = full row
#define HALF   (FPT / 2)          // elig burst split across the barrier

__global__ __launch_bounds__(NT)  // no min-blocks cap: regs ~56 (R9 optimum)
void snn_final_kernel(const float* __restrict__ x,
                      const float* __restrict__ syn,
                      const float* __restrict__ mp,
                      const float* __restrict__ thr,
                      const float* __restrict__ elig,
                      float* __restrict__ out) {
    __shared__ float red[NT / 32];
    const int o = blockIdx.x;
    const int t = threadIdx.x;

    const float4* x4 = reinterpret_cast<const float4*>(x);   // 32 KB, L1-resident
    const float4* s4 = reinterpret_cast<const float4*>(syn  + (size_t)o * IN_F);
    const float4* e4 = reinterpret_cast<const float4*>(elig + (size_t)o * IN_F);

    // ── Phase 1: front-batched full-row burst of syn ──
    float4 s[FPT];
    #pragma unroll
    for (int j = 0; j < FPT; j++)
        s[j] = __ldcs(&s4[t + j * NT]);          // 8 LDG.128 in flight

    float a0 = 0.0f, a1 = 0.0f, a2 = 0.0f, a3 = 0.0f;   // 4 independent chains
    #pragma unroll
    for (int j = 0; j < FPT; j++) {
        float4 xv = __ldg(&x4[t + j * NT]);      // L1 hit after warm-up
        a0 += (s[j].x > THR ? xv.x : 0.0f);
        a1 += (s[j].y > THR ? xv.y : 0.0f);
        a2 += (s[j].z > THR ? xv.z : 0.0f);
        a3 += (s[j].w > THR ? xv.w : 0.0f);
    }

    // First half of elig burst — in flight across the reduce/barrier
    float4 e[HALF];
    #pragma unroll
    for (int j = 0; j < HALF; j++)
        e[j] = __ldcs(&e4[t + j * NT]);

    float acc = (a0 + a1) + (a2 + a3);
    #pragma unroll
    for (int off = 16; off > 0; off >>= 1)
        acc += __shfl_down_sync(0xffffffffu, acc, off);
    if ((t & 31) == 0) red[t >> 5] = acc;
    __syncthreads();                             // first elig half still in flight

    // Second half issued immediately post-barrier — flies under finalize +
    // first-half consume/stores (uncapped regs let ptxas schedule it early).
    float4 e2[HALF];
    #pragma unroll
    for (int j = 0; j < HALF; j++)
        e2[j] = __ldcs(&e4[t + (HALF + j) * NT]);

    float cur = 0.0f;
    #pragma unroll
    for (int w = 0; w < NT / 32; w++) cur += red[w];
    const float v  = __ldg(mp + o) * 0.6f + cur;
    const float sp = (v >= __ldg(thr + o)) ? 1.0f : 0.0f;
    if (t == 0) {
        out[o] = sp;                             // spikes
        out[OUT_F + o] = v * (1.0f - sp) * 0.3f; // v_new
    }

    // ── Phase 2: consume both halves → trace ──
    float4* o4 = reinterpret_cast<float4*>(out + 2 * (size_t)OUT_F
                                               + (size_t)o * IN_F);
    #pragma unroll
    for (int j = 0; j < HALF; j++) {
        float4 xv = __ldg(&x4[t + j * NT]);
        float4 r;
        r.x = fminf(fmaxf(fmaf(e[j].x, 0.7f, sp * xv.x), 0.0f), 3.0f);
        r.y = fminf(fmaxf(fmaf(e[j].y, 0.7f, sp * xv.y), 0.0f), 3.0f);
        r.z = fminf(fmaxf(fmaf(e[j].z, 0.7f, sp * xv.z), 0.0f), 3.0f);
        r.w = fminf(fmaxf(fmaf(e[j].w, 0.7f, sp * xv.w), 0.0f), 3.0f);
        __stcs(&o4[t + j * NT], r);
    }
    #pragma unroll
    for (int j = 0; j < HALF; j++) {
        float4 xv = __ldg(&x4[t + (HALF + j) * NT]);
        float4 r;
        r.x = fminf(fmaxf(fmaf(e2[j].x, 0.7f, sp * xv.x), 0.0f), 3.0f);
        r.y = fminf(fmaxf(fmaf(e2[j].y, 0.7f, sp * xv.y), 0.0f), 3.0f);
        r.z = fminf(fmaxf(fmaf(e2[j].z, 0.7f, sp * xv.z), 0.0f), 3.0f);
        r.w = fminf(fmaxf(fmaf(e2[j].w, 0.7f, sp * xv.w), 0.0f), 3.0f);
        __stcs(&o4[t + (HALF + j) * NT], r);
    }
}

extern "C" void kernel_launch(void* const* d_in, const int* in_sizes, int n_in,
                              void* d_out, int out_size) {
    const float* x    = (const float*)d_in[0];  // spike_input [1, 8192]
    const float* syn  = (const float*)d_in[1];  // synapse_states [8192, 8192]
    const float* mp   = (const float*)d_in[2];  // membrane_potential [8192]
    const float* thr  = (const float*)d_in[3];  // adaptive_threshold [8192]
    const float* elig = (const float*)d_in[4];  // eligibility_trace [8192, 8192]
    float* out = (float*)d_out;                 // [spikes | v_new | trace_new]

    snn_final_kernel<<<OUT_F, NT>>>(x, syn, mp, thr, elig, out);
}